// round 4
// baseline (speedup 1.0000x reference)
#include <cuda_runtime.h>
#include <float.h>

// Fused: out[b,c,y,x] = relu( p1[b,c%128,y,x] + p2[b,c%64,y,x]
//                           + p3[b,c%32,y,x] + p4[b,c%16,y,x] + ff[b,c,y,x] )
// pk = non-overlapping max-pool of input_tensor_k.
//
// One CTA per (b, y, x-third): pools its 8-wide x-slice of all 4 tensors ONCE
// into SMEM (x-splits partition input reads exactly -> minimal HBM traffic),
// then assembles the 256-channel slice with float4 stores.
// 1152 CTAs x 256 threads, 8 CTAs/SM (regs<=32) -> single wave, 64 warps/SM,
// max CTA imbalance 8 vs avg 7.78 (2.8% tail).

#define NB 16
#define HW 24          // output spatial size
#define HX 8           // x extent per CTA (third of a row)
#define THREADS 256

__global__ __launch_bounds__(THREADS, 8)
void fused_ffblock_kernel(const float* __restrict__ t1,   // [16,128,48,48]
                          const float* __restrict__ t2,   // [16, 64,96,96]
                          const float* __restrict__ t3,   // [16, 32,192,192]
                          const float* __restrict__ t4,   // [16, 16,384,384]
                          const float* __restrict__ ff,   // [16,256,24,24]
                          float* __restrict__ out)        // [16,256,24,24]
{
    const int bx  = blockIdx.x;
    const int xh  = bx % 3;                  // x-third: [0,8), [8,16), [16,24)
    const int y   = (bx / 3) % HW;
    const int b   = bx / (3 * HW);
    const int tid = threadIdx.x;
    const int xbase = xh * HX;

    __shared__ __align__(16) float p4part[2 * 16 * HX];   // [half][c*HX + l]
    __shared__ __align__(16) float p3s[32 * HX];
    __shared__ __align__(16) float p2s[64 * HX];
    __shared__ __align__(16) float p1s[128 * HX];

    // ---- t4: k=16, 16 ch, input 384x384. 128 windows x 2 row-halves = 256
    // items, one per thread. Each thread: 8 rows x 4 float4 (512B).
    {
        const int h = tid >> 7;              // row half (0: rows 0-7, 1: rows 8-15)
        const int j = tid & 127;
        const int c = j >> 3, l = j & 7;
        const float* rowp = t4 + ((c + b * 16) * 384 + y * 16 + h * 8) * 384
                               + (xbase + l) * 16;
        float4 m = make_float4(-FLT_MAX, -FLT_MAX, -FLT_MAX, -FLT_MAX);
        #pragma unroll 2
        for (int r = 0; r < 8; ++r) {
            const float4* p = reinterpret_cast<const float4*>(rowp + r * 384);
            float4 v0 = p[0], v1 = p[1], v2 = p[2], v3 = p[3];
            m.x = fmaxf(m.x, fmaxf(fmaxf(v0.x, v1.x), fmaxf(v2.x, v3.x)));
            m.y = fmaxf(m.y, fmaxf(fmaxf(v0.y, v1.y), fmaxf(v2.y, v3.y)));
            m.z = fmaxf(m.z, fmaxf(fmaxf(v0.z, v1.z), fmaxf(v2.z, v3.z)));
            m.w = fmaxf(m.w, fmaxf(fmaxf(v0.w, v1.w), fmaxf(v2.w, v3.w)));
        }
        p4part[tid] = fmaxf(fmaxf(m.x, m.y), fmaxf(m.z, m.w));
    }

    // ---- t3: k=8, 32 ch, input 192x192. Exactly 256 items; 8 rows x 2 float4.
    {
        const int c = tid >> 3, l = tid & 7;
        const float* rowp = t3 + ((c + b * 32) * 192 + y * 8) * 192 + (xbase + l) * 8;
        float4 m = make_float4(-FLT_MAX, -FLT_MAX, -FLT_MAX, -FLT_MAX);
        #pragma unroll 2
        for (int r = 0; r < 8; ++r) {
            const float4* p = reinterpret_cast<const float4*>(rowp + r * 192);
            float4 v0 = p[0], v1 = p[1];
            m.x = fmaxf(m.x, fmaxf(v0.x, v1.x));
            m.y = fmaxf(m.y, fmaxf(v0.y, v1.y));
            m.z = fmaxf(m.z, fmaxf(v0.z, v1.z));
            m.w = fmaxf(m.w, fmaxf(v0.w, v1.w));
        }
        p3s[tid] = fmaxf(fmaxf(m.x, m.y), fmaxf(m.z, m.w));
    }

    // ---- t2: k=4, 64 ch, input 96x96. 512 items; 4 rows x 1 float4.
    #pragma unroll
    for (int i = tid; i < 64 * HX; i += THREADS) {
        const int c = i >> 3, l = i & 7;
        const float* rowp = t2 + ((c + b * 64) * 96 + y * 4) * 96 + (xbase + l) * 4;
        float4 m = make_float4(-FLT_MAX, -FLT_MAX, -FLT_MAX, -FLT_MAX);
        #pragma unroll
        for (int r = 0; r < 4; ++r) {
            float4 v = *reinterpret_cast<const float4*>(rowp + r * 96);
            m.x = fmaxf(m.x, v.x); m.y = fmaxf(m.y, v.y);
            m.z = fmaxf(m.z, v.z); m.w = fmaxf(m.w, v.w);
        }
        p2s[i] = fmaxf(fmaxf(m.x, m.y), fmaxf(m.z, m.w));
    }

    // ---- t1: k=2, 128 ch, input 48x48. Each item = 2 outputs via float4:
    // 128 * 4 = 512 items; 2 rows x 1 float4.
    #pragma unroll
    for (int i = tid; i < 128 * (HX / 2); i += THREADS) {
        const int c = i >> 2, xp = i & 3;    // xp = local x / 2
        const float* rowp = t1 + ((c + b * 128) * 48 + y * 2) * 48
                               + xbase * 2 + xp * 4;
        float4 v0 = *reinterpret_cast<const float4*>(rowp);
        float4 v1 = *reinterpret_cast<const float4*>(rowp + 48);
        p1s[c * HX + xp * 2 + 0] = fmaxf(fmaxf(v0.x, v0.y), fmaxf(v1.x, v1.y));
        p1s[c * HX + xp * 2 + 1] = fmaxf(fmaxf(v0.z, v0.w), fmaxf(v1.z, v1.w));
    }

    __syncthreads();

    // ---- assemble: 256 ch x 8 x, as 256 x 2 float4 items = 512.
    const int row_base = ((b * 256) * HW + y) * HW + xbase;
    #pragma unroll
    for (int j = tid; j < 256 * (HX / 4); j += THREADS) {
        const int c  = j >> 1;
        const int x0 = (j & 1) * 4;
        const int c1 = c & 127, c2 = c & 63, c3 = c & 31, c4 = c & 15;
        const int g  = row_base + c * (HW * HW) + x0;

        float4 f  = *reinterpret_cast<const float4*>(ff + g);
        float4 a1 = *reinterpret_cast<const float4*>(&p1s[c1 * HX + x0]);
        float4 a2 = *reinterpret_cast<const float4*>(&p2s[c2 * HX + x0]);
        float4 a3 = *reinterpret_cast<const float4*>(&p3s[c3 * HX + x0]);
        float4 h0 = *reinterpret_cast<const float4*>(&p4part[c4 * HX + x0]);
        float4 h1 = *reinterpret_cast<const float4*>(&p4part[128 + c4 * HX + x0]);

        float4 r;
        r.x = fmaxf(f.x + a1.x + a2.x + a3.x + fmaxf(h0.x, h1.x), 0.f);
        r.y = fmaxf(f.y + a1.y + a2.y + a3.y + fmaxf(h0.y, h1.y), 0.f);
        r.z = fmaxf(f.z + a1.z + a2.z + a3.z + fmaxf(h0.z, h1.z), 0.f);
        r.w = fmaxf(f.w + a1.w + a2.w + a3.w + fmaxf(h0.w, h1.w), 0.f);

        *reinterpret_cast<float4*>(out + g) = r;
    }
}

extern "C" void kernel_launch(void* const* d_in, const int* in_sizes, int n_in,
                              void* d_out, int out_size) {
    const float* t1 = (const float*)d_in[0];
    const float* t2 = (const float*)d_in[1];
    const float* t3 = (const float*)d_in[2];
    const float* t4 = (const float*)d_in[3];
    const float* ff = (const float*)d_in[4];
    float* out = (float*)d_out;

    dim3 grid(NB * HW * 3);   // 1152 CTAs: one per (batch, row, x-third)
    dim3 block(THREADS);
    fused_ffblock_kernel<<<grid, block>>>(t1, t2, t3, t4, ff, out);
}